// round 5
// baseline (speedup 1.0000x reference)
#include <cuda_runtime.h>
#include <cuda_bf16.h>
#include <math.h>
#include <stdint.h>

// Shapes (fixed)
#define D_  1024
#define B_  128
#define T_  256

#define KSTAGE  64                   // k per smem stage (128B bf16 rows)
#define GSTAGES 8                    // stages per warp-group (k-half = 512)
#define STAGE_BYTES 32768            // AHI 8K | ALO 8K | BHI 8K | BLO 8K
#define GROUP_SMEM  (3 * STAGE_BYTES)
#define SMEM_DYN    (2 * GROUP_SMEM) // 192 KB, 1 CTA/SM

// Device scratch (allocation-free)
__device__ unsigned short g_WcThi[4 * D_ * D_];   // combined W^T hi  [n][k]
__device__ unsigned short g_WcTlo[4 * D_ * D_];
__device__ unsigned short g_W1Thi[4 * D_ * D_];   // step-1 W^T hi
__device__ unsigned short g_W1Tlo[4 * D_ * D_];
__device__ unsigned short g_hHi[2][B_ * D_];      // h split ping-pong
__device__ unsigned short g_hLo[2][B_ * D_];
__device__ float          g_zero[B_ * D_];        // h0 = 0 (never written)

// ---------------------------------------------------------------------------
// PTX helpers (plain sm_80+ features only)
// ---------------------------------------------------------------------------
__device__ __forceinline__ uint32_t s2u(const void* p) {
    uint32_t a;
    asm("{ .reg .u64 t; cvta.to.shared.u64 t, %1; cvt.u32.u64 %0, t; }"
        : "=r"(a) : "l"(p));
    return a;
}
__device__ __forceinline__ void cpasync16(uint32_t dst, const void* src) {
    asm volatile("cp.async.cg.shared.global [%0], [%1], 16;" :: "r"(dst), "l"(src));
}
__device__ __forceinline__ void cp_commit() {
    asm volatile("cp.async.commit_group;" ::: "memory");
}
template <int N> __device__ __forceinline__ void cp_wait() {
    asm volatile("cp.async.wait_group %0;" :: "n"(N) : "memory");
}
__device__ __forceinline__ void barg(int id) {    // per-group named barrier
    asm volatile("bar.sync %0, 128;" :: "r"(id + 1) : "memory");
}
__device__ __forceinline__ void ldsm4(uint32_t* r, uint32_t addr) {
    asm volatile("ldmatrix.sync.aligned.m8n8.x4.shared.b16 {%0,%1,%2,%3}, [%4];"
        : "=r"(r[0]), "=r"(r[1]), "=r"(r[2]), "=r"(r[3]) : "r"(addr));
}
__device__ __forceinline__ void mma_bf16(float* c, const uint32_t* a,
                                         uint32_t b0, uint32_t b1) {
    asm volatile("mma.sync.aligned.m16n8k16.row.col.f32.bf16.bf16.f32 "
        "{%0,%1,%2,%3}, {%4,%5,%6,%7}, {%8,%9}, {%0,%1,%2,%3};"
        : "+f"(c[0]), "+f"(c[1]), "+f"(c[2]), "+f"(c[3])
        : "r"(a[0]), "r"(a[1]), "r"(a[2]), "r"(a[3]), "r"(b0), "r"(b1));
}
__device__ __forceinline__ uint32_t sw128(uint32_t off) {
    return off ^ ((off >> 3) & 0x70);
}

// ---------------------------------------------------------------------------
// Prologue: combined weights, transposed to [n][k] (n = 4*d + g),
// gates g: {Wz+Rz, Wr+Rr, Wh, Rh} (Wc)  /  {Wz, Wr, Wh, 0} (W1, for t=1).
// ---------------------------------------------------------------------------
__global__ void prep_weights(const float* __restrict__ Wk,
                             const float* __restrict__ Wr) {
    int i = blockIdx.x * blockDim.x + threadIdx.x;   // 4096 * 128 threads
    int n  = i >> 7;
    int k0 = (i & 127) * 8;
    int d = n >> 2, g = n & 3;
    long o = (long)n * D_ + k0;
    #pragma unroll
    for (int j = 0; j < 8; j++) {
        long src = (long)(k0 + j) * (3 * D_) + (long)g * D_ + d;
        float wc, w1;
        if (g == 3) {
            float rh = Wr[(long)(k0 + j) * (3 * D_) + 2 * D_ + d];
            wc = rh; w1 = 0.f;
        } else {
            float a = Wk[src];
            float b = Wr[src];
            w1 = a;
            wc = (g == 2) ? a : (a + b);
        }
        __nv_bfloat16 ch = __float2bfloat16(wc);
        __nv_bfloat16 cl = __float2bfloat16(wc - __bfloat162float(ch));
        __nv_bfloat16 oh = __float2bfloat16(w1);
        __nv_bfloat16 ol = __float2bfloat16(w1 - __bfloat162float(oh));
        g_WcThi[o + j] = __bfloat16_as_ushort(ch);
        g_WcTlo[o + j] = __bfloat16_as_ushort(cl);
        g_W1Thi[o + j] = __bfloat16_as_ushort(oh);
        g_W1Tlo[o + j] = __bfloat16_as_ushort(ol);
    }
}

// out[:,0,:] = x0 ; split x0 into h buffer 0
__global__ void prep_x0(const float* __restrict__ x, float* __restrict__ out) {
    int i = blockIdx.x * blockDim.x + threadIdx.x;   // B_*D_
    int b = i >> 10, d = i & (D_ - 1);
    float v = x[(long)b * D_ + d];
    out[(long)b * (T_ * D_) + d] = v;
    __nv_bfloat16 hi = __float2bfloat16(v);
    g_hHi[0][i] = __bfloat16_as_ushort(hi);
    g_hLo[0][i] = __bfloat16_as_ushort(__float2bfloat16(v - __bfloat162float(hi)));
}

// ---------------------------------------------------------------------------
// Stage loader: 128 threads of one warp-group fill one 32KB stage.
// ---------------------------------------------------------------------------
__device__ __forceinline__ void load_stage(
    uint32_t st, int k0,
    const unsigned short* __restrict__ Ahi, const unsigned short* __restrict__ Alo,
    const unsigned short* __restrict__ Bhi, const unsigned short* __restrict__ Blo,
    int mrow0, int nrow0, int gtid)
{
    #pragma unroll
    for (int t = 0; t < 4; t++) {
        int r   = t * 128 + gtid;      // 512 16B-chunks per tile
        int row = r >> 3, ch = r & 7;
        uint32_t sw = sw128((uint32_t)(row * 128 + ch * 16));
        const long ko = (long)k0 + ch * 8;
        cpasync16(st +         sw, Ahi + (long)(mrow0 + row) * D_ + ko);
        cpasync16(st + 8192  + sw, Alo + (long)(mrow0 + row) * D_ + ko);
        cpasync16(st + 16384 + sw, Bhi + (long)(nrow0 + row) * D_ + ko);
        cpasync16(st + 24576 + sw, Blo + (long)(nrow0 + row) * D_ + ko);
    }
}

// ---------------------------------------------------------------------------
// One GRU step. C[128,4096] = (Ahi+Alo) @ (Bhi+Blo)^T via 3 bf16 HMMA splits.
// Grid: 128 CTAs = 64 n-tiles (N=64) x 2 m-halves (M=64). 256 threads:
// two split-K warp-groups (k halves), each 2x2 warps, warp tile 32x32,
// private 3-deep cp.async pipeline. fp32 partial combine in smem.
// ---------------------------------------------------------------------------
extern __shared__ char dsm[];

__global__ __launch_bounds__(256, 1)
void gru_step_mma(const unsigned short* __restrict__ Ahi,
                  const unsigned short* __restrict__ Alo,
                  const unsigned short* __restrict__ Whi,
                  const unsigned short* __restrict__ Wlo,
                  const float* __restrict__ bias,
                  const float* __restrict__ h_old, int h_stride,
                  float* __restrict__ out_t,
                  unsigned short* __restrict__ nhi,
                  unsigned short* __restrict__ nlo)
{
    const uint32_t sbase = s2u(dsm);
    const int tid  = threadIdx.x;
    const int wid  = tid >> 5, lane = tid & 31;
    const int wg   = wid >> 2;                      // split-K group 0/1
    const int wl   = wid & 3;
    const int wm   = wl & 1,  wn   = wl >> 1;       // warp grid 2(m) x 2(n)
    const int gtid = tid & 127;
    const int nb   = blockIdx.x & 63;               // n-tile index
    const int mh   = blockIdx.x >> 6;               // m-half
    const int mrow0 = mh * 64;
    const int nrow0 = nb * 64;
    const uint32_t gbase = sbase + (uint32_t)wg * GROUP_SMEM;
    const int kb = wg * 512;                        // k-half base

    float acc[2][4][4];
    #pragma unroll
    for (int i = 0; i < 2; i++)
        #pragma unroll
        for (int j = 0; j < 4; j++)
            #pragma unroll
            for (int q = 0; q < 4; q++) acc[i][j][q] = 0.f;

    // per-lane ldmatrix geometry
    const int fr   = (lane & 7) + ((lane >> 3) & 1) * 8;  // row within 16
    const int fch  = (lane >> 4) * 16;                    // byte col half (k8)
    const uint32_t swz = (uint32_t)(lane & 7) << 4;       // SW128 row mask

    // Prime pipeline: stages 0..2 of this group's k-half
    load_stage(gbase,                   kb,              Ahi, Alo, Whi, Wlo, mrow0, nrow0, gtid); cp_commit();
    load_stage(gbase + STAGE_BYTES,     kb + KSTAGE,     Ahi, Alo, Whi, Wlo, mrow0, nrow0, gtid); cp_commit();
    load_stage(gbase + 2 * STAGE_BYTES, kb + 2 * KSTAGE, Ahi, Alo, Whi, Wlo, mrow0, nrow0, gtid); cp_commit();

    int buf = 0;
    for (int s = 0; s < GSTAGES; s++) {
        if (s <= 5)      cp_wait<2>();
        else if (s == 6) cp_wait<1>();
        else             cp_wait<0>();
        barg(wg);

        const uint32_t st = gbase + (uint32_t)buf * STAGE_BYTES;
        const uint32_t aHi = st, aLo = st + 8192, bHi = st + 16384, bLo = st + 24576;

        #pragma unroll
        for (int kq = 0; kq < 4; kq++) {
            const uint32_t c = (uint32_t)(kq * 32 + fch) ^ swz;
            uint32_t ah[2][4], al[2][4], bh[2][4], bl[2][4];
            #pragma unroll
            for (int mt = 0; mt < 2; mt++) {
                uint32_t ro = (uint32_t)((wm * 32 + mt * 16 + fr) * 128) + c;
                ldsm4(ah[mt], aHi + ro);
                ldsm4(al[mt], aLo + ro);
            }
            #pragma unroll
            for (int np = 0; np < 2; np++) {
                uint32_t ro = (uint32_t)((wn * 32 + np * 16 + fr) * 128) + c;
                ldsm4(bh[np], bHi + ro);
                ldsm4(bl[np], bLo + ro);
            }
            #pragma unroll
            for (int mt = 0; mt < 2; mt++)
                #pragma unroll
                for (int nt = 0; nt < 4; nt++) {
                    const int np = nt >> 1, j = nt & 1;
                    mma_bf16(acc[mt][nt], ah[mt], bh[np][j], bh[np][j + 2]);
                    mma_bf16(acc[mt][nt], ah[mt], bl[np][j], bl[np][j + 2]);
                    mma_bf16(acc[mt][nt], al[mt], bh[np][j], bh[np][j + 2]);
                }
        }
        barg(wg);
        if (s + 3 < GSTAGES) {
            load_stage(st, kb + (s + 3) * KSTAGE, Ahi, Alo, Whi, Wlo, mrow0, nrow0, gtid);
            cp_commit();
        }
        buf = buf + 1; if (buf == 3) buf = 0;
    }

    // -------- split-K combine: group 1 -> smem, group 0 adds --------
    const uint32_t comb = sbase + GROUP_SMEM;   // reuse group-1 buffer space
    if (wg == 1) {
        #pragma unroll
        for (int mt = 0; mt < 2; mt++)
            #pragma unroll
            for (int nt = 0; nt < 4; nt++) {
                int r0 = wm * 32 + mt * 16 + (lane >> 2);
                int c0 = wn * 32 + nt * 8 + 2 * (lane & 3);
                uint32_t ad = comb + (uint32_t)((r0 * 64 + c0) << 2);
                asm volatile("st.shared.v2.f32 [%0], {%1,%2};"
                             :: "r"(ad), "f"(acc[mt][nt][0]), "f"(acc[mt][nt][1]));
                asm volatile("st.shared.v2.f32 [%0], {%1,%2};"
                             :: "r"(ad + 2048), "f"(acc[mt][nt][2]), "f"(acc[mt][nt][3]));
            }
    }
    __syncthreads();
    if (wg == 1) return;

    #pragma unroll
    for (int mt = 0; mt < 2; mt++)
        #pragma unroll
        for (int nt = 0; nt < 4; nt++) {
            int r0 = wm * 32 + mt * 16 + (lane >> 2);
            int c0 = wn * 32 + nt * 8 + 2 * (lane & 3);
            uint32_t ad = comb + (uint32_t)((r0 * 64 + c0) << 2);
            float p0, p1, p2, p3;
            asm volatile("ld.shared.v2.f32 {%0,%1}, [%2];"
                         : "=f"(p0), "=f"(p1) : "r"(ad));
            asm volatile("ld.shared.v2.f32 {%0,%1}, [%2];"
                         : "=f"(p2), "=f"(p3) : "r"(ad + 2048));
            acc[mt][nt][0] += p0; acc[mt][nt][1] += p1;
            acc[mt][nt][2] += p2; acc[mt][nt][3] += p3;
        }

    // ---------------- GRU gate epilogue (group 0 only) ----------------
    const int g     = lane >> 2;
    const int odd   = lane & 1;
    const int tg2   = (lane >> 1) & 1;
    const int dbase = nb * 16 + wn * 8;
    const int rowb  = mh * 64 + wm * 32 + g + odd * 8;

    #pragma unroll
    for (int mt = 0; mt < 2; mt++) {
        const int row = rowb + mt * 16;
        const float* ho = h_old + (long)row * h_stride;
        float* po = out_t + (long)row * (T_ * D_);
        unsigned short* phi = nhi + (long)row * D_;
        unsigned short* plo = nlo + (long)row * D_;
        #pragma unroll
        for (int nt = 0; nt < 4; nt++) {
            float* a = acc[mt][nt];
            float v0 = odd ? a[0] : a[2];
            float v1 = odd ? a[1] : a[3];
            float rx0 = __shfl_xor_sync(0xffffffffu, v0, 1);
            float rx1 = __shfl_xor_sync(0xffffffffu, v1, 1);
            float az, ar, ahv, agv;
            if (!odd) { az = a[0]; ar = a[1]; ahv = rx0;  agv = rx1;  }
            else      { az = rx0; ar = rx1;  ahv = a[2];  agv = a[3]; }
            const int d = dbase + nt * 2 + tg2;
            float z    = 1.f / (1.f + __expf(-(az + bias[d])));
            float rr   = 1.f / (1.f + __expf(-(ar + bias[D_ + d])));
            float cand = tanhf(ahv + bias[2 * D_ + d] + rr * agv);
            float h    = z * ho[d] + (1.f - z) * cand;
            po[d] = h;
            __nv_bfloat16 hb = __float2bfloat16(h);
            phi[d] = __bfloat16_as_ushort(hb);
            plo[d] = __bfloat16_as_ushort(
                __float2bfloat16(h - __bfloat162float(hb)));
        }
    }
}

// ---------------------------------------------------------------------------
extern "C" void kernel_launch(void* const* d_in, const int* in_sizes, int n_in,
                              void* d_out, int out_size) {
    const float* x    = (const float*)d_in[0];
    const float* Wk   = (const float*)d_in[1];
    const float* Wr   = (const float*)d_in[2];
    const float* bias = (const float*)d_in[3];
    float* out = (float*)d_out;

    unsigned short *WcHi, *WcLo, *W1Hi, *W1Lo, *hHi, *hLo;
    float* zero;
    cudaGetSymbolAddress((void**)&WcHi, g_WcThi);
    cudaGetSymbolAddress((void**)&WcLo, g_WcTlo);
    cudaGetSymbolAddress((void**)&W1Hi, g_W1Thi);
    cudaGetSymbolAddress((void**)&W1Lo, g_W1Tlo);
    cudaGetSymbolAddress((void**)&hHi,  g_hHi);
    cudaGetSymbolAddress((void**)&hLo,  g_hLo);
    cudaGetSymbolAddress((void**)&zero, g_zero);

    cudaFuncSetAttribute(gru_step_mma,
                         cudaFuncAttributeMaxDynamicSharedMemorySize, SMEM_DYN);

    prep_weights<<<(4 * D_ * 128) / 256, 256>>>(Wk, Wr);
    prep_x0<<<(B_ * D_) / 256, 256>>>(x, out);

    // t = 1: A = x0 split (buf 0), h_old = 0, weights W1 (Rh = 0)
    gru_step_mma<<<128, 256, SMEM_DYN>>>(
        hHi, hLo, W1Hi, W1Lo, bias, zero, D_,
        out + D_, hHi + (size_t)B_ * D_, hLo + (size_t)B_ * D_);

    // t = 2..T-1: A = h_{t-1} split, h_old = out[:, t-1, :]
    for (int t = 2; t < T_; t++) {
        int rp = (t - 1) & 1, wp = t & 1;
        gru_step_mma<<<128, 256, SMEM_DYN>>>(
            hHi + (size_t)rp * B_ * D_, hLo + (size_t)rp * B_ * D_,
            WcHi, WcLo, bias,
            out + (size_t)(t - 1) * D_, T_ * D_,
            out + (size_t)t * D_,
            hHi + (size_t)wp * B_ * D_, hLo + (size_t)wp * B_ * D_);
    }
}

// round 6
// speedup vs baseline: 1.4986x; 1.4986x over previous
#include <cuda_runtime.h>
#include <cuda_bf16.h>
#include <math.h>
#include <stdint.h>

// Shapes (fixed)
#define D_  1024
#define B_  128
#define T_  256

#define KSTAGE  64                   // k per smem stage (128B bf16 rows)
#define NSTAGES (D_ / KSTAGE)        // 16
#define STAGE_BYTES 32768            // AHI 8K | ALO 8K | BHI 8K | BLO 8K
#define NBUF 4
#define SMEM_DYN (NBUF * STAGE_BYTES)   // 128 KB, 1 CTA/SM

// Device scratch (allocation-free)
__device__ unsigned short g_WcThi[4 * D_ * D_];   // combined W^T hi  [n][k]
__device__ unsigned short g_WcTlo[4 * D_ * D_];
__device__ unsigned short g_W1Thi[4 * D_ * D_];   // step-1 W^T hi
__device__ unsigned short g_W1Tlo[4 * D_ * D_];
__device__ unsigned short g_hHi[2][B_ * D_];      // h split ping-pong
__device__ unsigned short g_hLo[2][B_ * D_];
__device__ float          g_zero[B_ * D_];        // h0 = 0 (never written)

// ---------------------------------------------------------------------------
// PTX helpers (plain sm_80+ features only)
// ---------------------------------------------------------------------------
__device__ __forceinline__ uint32_t s2u(const void* p) {
    uint32_t a;
    asm("{ .reg .u64 t; cvta.to.shared.u64 t, %1; cvt.u32.u64 %0, t; }"
        : "=r"(a) : "l"(p));
    return a;
}
__device__ __forceinline__ void cpasync16(uint32_t dst, const void* src) {
    asm volatile("cp.async.cg.shared.global [%0], [%1], 16;" :: "r"(dst), "l"(src));
}
__device__ __forceinline__ void cp_commit() {
    asm volatile("cp.async.commit_group;" ::: "memory");
}
template <int N> __device__ __forceinline__ void cp_wait() {
    asm volatile("cp.async.wait_group %0;" :: "n"(N) : "memory");
}
__device__ __forceinline__ void ldsm4(uint32_t* r, uint32_t addr) {
    asm volatile("ldmatrix.sync.aligned.m8n8.x4.shared.b16 {%0,%1,%2,%3}, [%4];"
        : "=r"(r[0]), "=r"(r[1]), "=r"(r[2]), "=r"(r[3]) : "r"(addr));
}
__device__ __forceinline__ void mma_bf16(float* c, const uint32_t* a,
                                         uint32_t b0, uint32_t b1) {
    asm volatile("mma.sync.aligned.m16n8k16.row.col.f32.bf16.bf16.f32 "
        "{%0,%1,%2,%3}, {%4,%5,%6,%7}, {%8,%9}, {%0,%1,%2,%3};"
        : "+f"(c[0]), "+f"(c[1]), "+f"(c[2]), "+f"(c[3])
        : "r"(a[0]), "r"(a[1]), "r"(a[2]), "r"(a[3]), "r"(b0), "r"(b1));
}
__device__ __forceinline__ uint32_t sw128(uint32_t off) {
    return off ^ ((off >> 3) & 0x70);
}

// ---------------------------------------------------------------------------
// Prologue: combined weights, transposed to [n][k] (n = 4*d + g),
// gates g: {Wz+Rz, Wr+Rr, Wh, Rh} (Wc)  /  {Wz, Wr, Wh, 0} (W1, for t=1).
// ---------------------------------------------------------------------------
__global__ void prep_weights(const float* __restrict__ Wk,
                             const float* __restrict__ Wr) {
    int i = blockIdx.x * blockDim.x + threadIdx.x;   // 4096 * 128 threads
    int n  = i >> 7;
    int k0 = (i & 127) * 8;
    int d = n >> 2, g = n & 3;
    long o = (long)n * D_ + k0;
    #pragma unroll
    for (int j = 0; j < 8; j++) {
        long src = (long)(k0 + j) * (3 * D_) + (long)g * D_ + d;
        float wc, w1;
        if (g == 3) {
            float rh = Wr[(long)(k0 + j) * (3 * D_) + 2 * D_ + d];
            wc = rh; w1 = 0.f;
        } else {
            float a = Wk[src];
            float b = Wr[src];
            w1 = a;
            wc = (g == 2) ? a : (a + b);
        }
        __nv_bfloat16 ch = __float2bfloat16(wc);
        __nv_bfloat16 cl = __float2bfloat16(wc - __bfloat162float(ch));
        __nv_bfloat16 oh = __float2bfloat16(w1);
        __nv_bfloat16 ol = __float2bfloat16(w1 - __bfloat162float(oh));
        g_WcThi[o + j] = __bfloat16_as_ushort(ch);
        g_WcTlo[o + j] = __bfloat16_as_ushort(cl);
        g_W1Thi[o + j] = __bfloat16_as_ushort(oh);
        g_W1Tlo[o + j] = __bfloat16_as_ushort(ol);
    }
}

// out[:,0,:] = x0 ; split x0 into h buffer 0
__global__ void prep_x0(const float* __restrict__ x, float* __restrict__ out) {
    int i = blockIdx.x * blockDim.x + threadIdx.x;   // B_*D_
    int b = i >> 10, d = i & (D_ - 1);
    float v = x[(long)b * D_ + d];
    out[(long)b * (T_ * D_) + d] = v;
    __nv_bfloat16 hi = __float2bfloat16(v);
    g_hHi[0][i] = __bfloat16_as_ushort(hi);
    g_hLo[0][i] = __bfloat16_as_ushort(__float2bfloat16(v - __bfloat162float(hi)));
}

// ---------------------------------------------------------------------------
// Stage loader: all 256 threads fill one 32KB stage (8 x 16B per thread).
// ---------------------------------------------------------------------------
__device__ __forceinline__ void load_stage(
    uint32_t st, int k0,
    const unsigned short* __restrict__ Ahi, const unsigned short* __restrict__ Alo,
    const unsigned short* __restrict__ Bhi, const unsigned short* __restrict__ Blo,
    int mrow0, int nrow0, int tid)
{
    #pragma unroll
    for (int t = 0; t < 2; t++) {
        int r   = t * 256 + tid;       // 512 16B-chunks per 8KB tile
        int row = r >> 3, ch = r & 7;
        uint32_t sw = sw128((uint32_t)(row * 128 + ch * 16));
        const long ko = (long)k0 + ch * 8;
        cpasync16(st +         sw, Ahi + (long)(mrow0 + row) * D_ + ko);
        cpasync16(st + 8192  + sw, Alo + (long)(mrow0 + row) * D_ + ko);
        cpasync16(st + 16384 + sw, Bhi + (long)(nrow0 + row) * D_ + ko);
        cpasync16(st + 24576 + sw, Blo + (long)(nrow0 + row) * D_ + ko);
    }
}

// ---------------------------------------------------------------------------
// One GRU step. C[128,4096] = (Ahi+Alo) @ (Bhi+Blo)^T via 3 bf16 HMMA splits.
// Grid: 128 CTAs = 64 n-tiles (N=64) x 2 m-halves (M=64). 256 threads,
// 8 warps in a 4(m) x 2(n) grid, warp tile 16x32, shared 4-deep pipeline,
// ONE __syncthreads per stage (refill into the just-freed buffer).
// ---------------------------------------------------------------------------
extern __shared__ char dsm[];

__global__ __launch_bounds__(256, 1)
void gru_step_mma(const unsigned short* __restrict__ Ahi,
                  const unsigned short* __restrict__ Alo,
                  const unsigned short* __restrict__ Whi,
                  const unsigned short* __restrict__ Wlo,
                  const float* __restrict__ bias,
                  const float* __restrict__ h_old, int h_stride,
                  float* __restrict__ out_t,
                  unsigned short* __restrict__ nhi,
                  unsigned short* __restrict__ nlo)
{
    const uint32_t sbase = s2u(dsm);
    const int tid  = threadIdx.x;
    const int wid  = tid >> 5, lane = tid & 31;
    const int wm   = wid & 3;                       // 4 m-warps
    const int wn   = wid >> 2;                      // 2 n-warps
    const int nb   = blockIdx.x & 63;               // n-tile index
    const int mh   = blockIdx.x >> 6;               // m-half
    const int mrow0 = mh * 64;
    const int nrow0 = nb * 64;

    float acc[4][4];                                // [nt(n8)][4]
    #pragma unroll
    for (int j = 0; j < 4; j++)
        #pragma unroll
        for (int q = 0; q < 4; q++) acc[j][q] = 0.f;

    // per-lane ldmatrix geometry
    const int fr   = (lane & 7) + ((lane >> 3) & 1) * 8;  // row within 16
    const int fch  = (lane >> 4) * 16;                    // byte col half (k8)
    const uint32_t swz = (uint32_t)(lane & 7) << 4;       // SW128 row mask

    // Prime pipeline: stages 0..2
    load_stage(sbase,                   0,          Ahi, Alo, Whi, Wlo, mrow0, nrow0, tid); cp_commit();
    load_stage(sbase + STAGE_BYTES,     KSTAGE,     Ahi, Alo, Whi, Wlo, mrow0, nrow0, tid); cp_commit();
    load_stage(sbase + 2 * STAGE_BYTES, 2 * KSTAGE, Ahi, Alo, Whi, Wlo, mrow0, nrow0, tid); cp_commit();

    int buf = 0;
    for (int s = 0; s < NSTAGES; s++) {
        if (s <= NSTAGES - 3)      cp_wait<2>();
        else if (s == NSTAGES - 2) cp_wait<1>();
        else                       cp_wait<0>();
        __syncthreads();

        // refill the buffer freed at stage s-1 with stage s+3
        if (s + 3 < NSTAGES) {
            int nxt = buf + 3; if (nxt >= NBUF) nxt -= NBUF;
            load_stage(sbase + (uint32_t)nxt * STAGE_BYTES, (s + 3) * KSTAGE,
                       Ahi, Alo, Whi, Wlo, mrow0, nrow0, tid);
            cp_commit();
        }

        const uint32_t st = sbase + (uint32_t)buf * STAGE_BYTES;
        const uint32_t aHi = st, aLo = st + 8192, bHi = st + 16384, bLo = st + 24576;

        #pragma unroll
        for (int kq = 0; kq < 4; kq++) {
            const uint32_t c = (uint32_t)(kq * 32 + fch) ^ swz;
            uint32_t ah[4], al[4], bh[2][4], bl[2][4];
            {
                uint32_t ro = (uint32_t)((wm * 16 + fr) * 128) + c;
                ldsm4(ah, aHi + ro);
                ldsm4(al, aLo + ro);
            }
            #pragma unroll
            for (int np = 0; np < 2; np++) {
                uint32_t ro = (uint32_t)((wn * 32 + np * 16 + fr) * 128) + c;
                ldsm4(bh[np], bHi + ro);
                ldsm4(bl[np], bLo + ro);
            }
            #pragma unroll
            for (int nt = 0; nt < 4; nt++) {
                const int np = nt >> 1, j = nt & 1;
                mma_bf16(acc[nt], ah, bh[np][j], bh[np][j + 2]);
                mma_bf16(acc[nt], ah, bl[np][j], bl[np][j + 2]);
                mma_bf16(acc[nt], al, bh[np][j], bh[np][j + 2]);
            }
        }
        buf = buf + 1; if (buf == NBUF) buf = 0;
    }

    // ---------------- GRU gate epilogue ----------------
    // Even-tg lanes hold gates {z,r}, odd-tg lanes {h,hh} of the same d.
    // One shfl_xor(1) exchange; even lane finishes row g, odd lane row g+8.
    const int g     = lane >> 2;
    const int odd   = lane & 1;
    const int tg2   = (lane >> 1) & 1;
    const int dbase = nb * 16 + wn * 8;
    const int row   = mh * 64 + wm * 16 + g + odd * 8;

    {
        const float* ho = h_old + (long)row * h_stride;
        float* po = out_t + (long)row * (T_ * D_);
        unsigned short* phi = nhi + (long)row * D_;
        unsigned short* plo = nlo + (long)row * D_;
        #pragma unroll
        for (int nt = 0; nt < 4; nt++) {
            float* a = acc[nt];
            float v0 = odd ? a[0] : a[2];
            float v1 = odd ? a[1] : a[3];
            float rx0 = __shfl_xor_sync(0xffffffffu, v0, 1);
            float rx1 = __shfl_xor_sync(0xffffffffu, v1, 1);
            float az, ar, ahv, agv;
            if (!odd) { az = a[0]; ar = a[1]; ahv = rx0;  agv = rx1;  }
            else      { az = rx0; ar = rx1;  ahv = a[2];  agv = a[3]; }
            const int d = dbase + nt * 2 + tg2;
            float z    = 1.f / (1.f + __expf(-(az + bias[d])));
            float rr   = 1.f / (1.f + __expf(-(ar + bias[D_ + d])));
            float cand = tanhf(ahv + bias[2 * D_ + d] + rr * agv);
            float h    = z * ho[d] + (1.f - z) * cand;
            po[d] = h;
            __nv_bfloat16 hb = __float2bfloat16(h);
            phi[d] = __bfloat16_as_ushort(hb);
            plo[d] = __bfloat16_as_ushort(
                __float2bfloat16(h - __bfloat162float(hb)));
        }
    }
}

// ---------------------------------------------------------------------------
extern "C" void kernel_launch(void* const* d_in, const int* in_sizes, int n_in,
                              void* d_out, int out_size) {
    const float* x    = (const float*)d_in[0];
    const float* Wk   = (const float*)d_in[1];
    const float* Wr   = (const float*)d_in[2];
    const float* bias = (const float*)d_in[3];
    float* out = (float*)d_out;

    unsigned short *WcHi, *WcLo, *W1Hi, *W1Lo, *hHi, *hLo;
    float* zero;
    cudaGetSymbolAddress((void**)&WcHi, g_WcThi);
    cudaGetSymbolAddress((void**)&WcLo, g_WcTlo);
    cudaGetSymbolAddress((void**)&W1Hi, g_W1Thi);
    cudaGetSymbolAddress((void**)&W1Lo, g_W1Tlo);
    cudaGetSymbolAddress((void**)&hHi,  g_hHi);
    cudaGetSymbolAddress((void**)&hLo,  g_hLo);
    cudaGetSymbolAddress((void**)&zero, g_zero);

    cudaFuncSetAttribute(gru_step_mma,
                         cudaFuncAttributeMaxDynamicSharedMemorySize, SMEM_DYN);

    prep_weights<<<(4 * D_ * 128) / 256, 256>>>(Wk, Wr);
    prep_x0<<<(B_ * D_) / 256, 256>>>(x, out);

    // t = 1: A = x0 split (buf 0), h_old = 0, weights W1 (Rh = 0)
    gru_step_mma<<<128, 256, SMEM_DYN>>>(
        hHi, hLo, W1Hi, W1Lo, bias, zero, D_,
        out + D_, hHi + (size_t)B_ * D_, hLo + (size_t)B_ * D_);

    // t = 2..T-1: A = h_{t-1} split, h_old = out[:, t-1, :]
    for (int t = 2; t < T_; t++) {
        int rp = (t - 1) & 1, wp = t & 1;
        gru_step_mma<<<128, 256, SMEM_DYN>>>(
            hHi + (size_t)rp * B_ * D_, hLo + (size_t)rp * B_ * D_,
            WcHi, WcLo, bias,
            out + (size_t)(t - 1) * D_, T_ * D_,
            out + (size_t)t * D_,
            hHi + (size_t)wp * B_ * D_, hLo + (size_t)wp * B_ * D_);
    }
}